// round 9
// baseline (speedup 1.0000x reference)
#include <cuda_runtime.h>
#include <cuda_fp16.h>
#include <cstdint>

#define NN 20000
#define MM 64
#define WL 8
#define NPAIRS (MM*NN*WL)      /* 10,240,000 pairs per X tensor */
#define NPB 32                 /* n's per chunk */
#define NCHUNK (NN/NPB)        /* 625 */
#define NBLK 148               /* one block per SM */
#define NT 1024                /* 32 warps */

// ---- shared memory layout (bytes) ----
#define SZ_TAB   (NN*8)          /* 160000: uint2 = {half2(b0,b1), half2(b2,b3)} */
#define OFF_F1   SZ_TAB          /* 160000 */
#define SZ_F1    (MM*33*8)       /* 16896 : F1[j][n] half4 (uint2), pad 33 */
#define OFF_F2   (OFF_F1+SZ_F1)  /* 176896 */
#define SZ_F2    (NPB*67*16)     /* 34304 : F2[n][k] float4, pad 67 */
#define OFF_PIP  (OFF_F2+SZ_F2)  /* 211200 */
#define SZ_PIP   (2048*4)        /* 8192  : piP[kp*64+j] half2 */
#define OFF_P12  (OFF_PIP+SZ_PIP)/* 219392 */
#define SZ_P12   (2*MM*4)        /* 512   */
#define OFF_RED  (OFF_P12+SZ_P12)/* 219904 */
#define SZ_RED   (NPB*2*16)      /* 1024  : float4[32][2] */
#define SMEM_TOTAL (OFF_RED+SZ_RED)  /* 220928 */

typedef unsigned long long ull;

// ---------------- device scratch (static) ------------------------------------
__device__ unsigned g_cx1[NPAIRS];   // packed (i0 | i1<<16)
__device__ unsigned g_cx2[NPAIRS];
__device__ uint2    g_tabB[NN];      // intermediate a after iter 0 (half x 4 batches)
__device__ int      g_tick[2] = {0, 0};

// ---------------- f32x2 helpers ----------------------------------------------
__device__ __forceinline__ ull pack2(float lo, float hi) {
    ull r; asm("mov.b64 %0, {%1, %2};" : "=l"(r) : "f"(lo), "f"(hi)); return r;
}
__device__ __forceinline__ float2 unpack2(ull v) {
    float2 f; asm("mov.b64 {%0, %1}, %2;" : "=f"(f.x), "=f"(f.y) : "l"(v)); return f;
}
__device__ __forceinline__ void fma2(ull& d, ull a, ull b) {
    asm("fma.rn.f32x2 %0, %1, %2, %0;" : "+l"(d) : "l"(a), "l"(b));
}

// ---------------- gather: 8 independent products + max tree -------------------
__device__ __forceinline__ void gath8(const unsigned* pk, const uint2* __restrict__ tab,
                                      __half2& ga, __half2& gb) {
    __half2 px[8], py[8];
    #pragma unroll
    for (int w = 0; w < 8; w++) {
        uint2 A = tab[pk[w] & 0xFFFFu];
        uint2 B = tab[pk[w] >> 16];
        px[w] = __hmul2(*(__half2*)&A.x, *(__half2*)&B.x);
        py[w] = __hmul2(*(__half2*)&A.y, *(__half2*)&B.y);
    }
    #pragma unroll
    for (int s = 4; s > 0; s >>= 1) {
        #pragma unroll
        for (int w = 0; w < s; w++) {
            px[w] = __hmax2(px[w], px[w + s]);
            py[w] = __hmax2(py[w], py[w + s]);
        }
    }
    ga = px[0]; gb = py[0];
}

// ---------------- main iteration kernel --------------------------------------
template<int ITER>
__global__ void __launch_bounds__(NT, 1) k_iter(const float* __restrict__ a0,
                                                const float* __restrict__ Wm,
                                                const void* __restrict__ x1,
                                                const void* __restrict__ x2,
                                                float* __restrict__ out) {
    extern __shared__ char smem[];
    uint2*    tabh = (uint2*)smem;                    // [NN]
    uint2*    F1h  = (uint2*) (smem + OFF_F1);        // [64][33] half4
    float*    sp   = (float*) (smem + OFF_F1);        // [4096] softmax scratch (preamble)
    float4*   F2f  = (float4*)(smem + OFF_F2);        // [32][67]
    __half2*  piPh = (__half2*)(smem + OFF_PIP);      // [32*64]
    float*    pi1s = (float*) (smem + OFF_P12);
    float*    pi2s = pi1s + MM;
    float4*   red4 = (float4*)(smem + OFF_RED);       // [32][2]
    float*    redf = (float*) (smem + OFF_RED);
    __shared__ int s_next;

    const int tid  = threadIdx.x;
    const int warp = tid >> 5, lane = tid & 31;

    // reset the OTHER iter's ticket for the next launch/replay
    if (blockIdx.x == 0 && tid == 0) g_tick[ITER ^ 1] = 0;

    // ===== preamble: half 4-batch a-table =====
    if (ITER == 0) {
        for (int i = tid; i < NN; i += NT) {
            __half2 h01 = __floats2half2_rn(__ldg(a0 + i),        __ldg(a0 + NN + i));
            __half2 h23 = __floats2half2_rn(__ldg(a0 + 2*NN + i), __ldg(a0 + 3*NN + i));
            tabh[i] = make_uint2(*(unsigned*)&h01, *(unsigned*)&h23);
        }
    } else {
        for (int i = tid; i < NN; i += NT) tabh[i] = g_tabB[i];
    }

    // ===== preamble: softmax over 64x64 W =====
    {
        float v4[4];
        float lm = -1e30f;
        #pragma unroll
        for (int t = 0; t < 4; t++) {
            float v = __ldg(Wm + tid + t*NT);
            v4[t] = v;
            lm = fmaxf(lm, v);
        }
        #pragma unroll
        for (int off = 16; off > 0; off >>= 1)
            lm = fmaxf(lm, __shfl_xor_sync(0xFFFFFFFFu, lm, off));
        if (lane == 0) redf[warp] = lm;
        __syncthreads();
        float m = -1e30f;
        #pragma unroll
        for (int w = 0; w < 32; w++) m = fmaxf(m, redf[w]);
        __syncthreads();
        float ls = 0.f;
        #pragma unroll
        for (int t = 0; t < 4; t++) {
            float e = expf(v4[t] - m);
            sp[tid + t*NT] = e;
            ls += e;
        }
        #pragma unroll
        for (int off = 16; off > 0; off >>= 1)
            ls += __shfl_xor_sync(0xFFFFFFFFu, ls, off);
        if (lane == 0) redf[32 + warp] = ls;
        __syncthreads();
        float tot = 0.f;
        #pragma unroll
        for (int w = 0; w < 32; w++) tot += redf[32 + w];
        const float inv = 1.f / tot;

        for (int i = tid; i < 2048; i += NT) {
            int kp = i >> 6, j = i & 63;
            piPh[i] = __floats2half2_rn(sp[j*MM + 2*kp] * inv, sp[j*MM + 2*kp + 1] * inv);
        }
        if (tid < MM) {
            float s = 0.f;
            #pragma unroll 16
            for (int k = 0; k < MM; k++) s += sp[tid*MM + k];
            pi1s[tid] = s * inv;
        } else if (tid < 2*MM) {
            int k = tid - MM;
            float s = 0.f;
            #pragma unroll 16
            for (int j = 0; j < MM; j++) s += sp[j*MM + k];
            pi2s[k] = s * inv;
        }
    }

    // ===== preamble: dtype probe (iter 0 only) =====
    int is64 = 0;
    if (ITER == 0) {
        const unsigned* x1u = (const unsigned*)x1;
        int nz = (x1u[2*tid + 1] != 0u) | (x1u[2*(tid + NT) + 1] != 0u);
        is64 = !__syncthreads_or(nz);
    }

    const int jj = tid & 63, g8 = tid >> 6;   // phase-2 mapping (g8: 0..15)
    const int half = warp & 1;
    int* tick = &g_tick[ITER];

    if (tid == 0) s_next = atomicAdd(tick, 1);     // first ticket
    int pend_n0 = -1;

    for (;;) {
        __syncthreads();                            // s_next + red4 ready, F free
        const int chunk = s_next;

        // ---- deferred finalize of previous chunk (overlaps next phase 1) ----
        if (pend_n0 >= 0) {
            if (ITER == 0) {
                if (tid < NPB) {
                    const int n = pend_n0 + tid;
                    float4 d0 = red4[tid*2], d1 = red4[tid*2 + 1];
                    uint2 u = tabh[n];
                    float2 a01 = __half22float2(*(__half2*)&u.x);
                    float2 a23 = __half22float2(*(__half2*)&u.y);
                    __half2 h01 = __floats2half2_rn(
                        1.f - (1.f - a01.x) * (1.f - (d0.x + d1.x)),
                        1.f - (1.f - a01.y) * (1.f - (d0.y + d1.y)));
                    __half2 h23 = __floats2half2_rn(
                        1.f - (1.f - a23.x) * (1.f - (d0.z + d1.z)),
                        1.f - (1.f - a23.y) * (1.f - (d0.w + d1.w)));
                    g_tabB[n] = make_uint2(*(unsigned*)&h01, *(unsigned*)&h23);
                }
            } else {
                if (tid < 4*NPB) {
                    const int b = tid >> 5, nl = tid & 31;
                    const int n = pend_n0 + nl;
                    float dv = redf[nl*8 + b] + redf[nl*8 + 4 + b];
                    float av = __half2float(((const __half*)smem)[n*4 + b]);
                    out[b*NN + n] = 1.f - (1.f - av) * (1.f - dv);
                }
            }
        }
        if (chunk >= NCHUNK) break;
        const int n0 = chunk * NPB;

        // ---- hidden ticket for the NEXT chunk (warp 31, during phase 1) ----
        if (tid == NT - 32 && lane == 0) s_next = atomicAdd(tick, 1);

        // ======== phase 1: 4-batch half gather-max ========
        #pragma unroll
        for (int p = 0; p < 2; p++) {
            const int j = p*32 + warp;
            const size_t pb = ((size_t)j * NN + n0 + lane) * WL;
            unsigned pk1[8], pk2[8];
            if (ITER == 0) {
                if (is64) {
                    const uint4* c1 = (const uint4*)x1 + pb;
                    const uint4* c2 = (const uint4*)x2 + pb;
                    #pragma unroll
                    for (int w = 0; w < 8; w++) { uint4 v = __ldcs(c1 + w); pk1[w] = v.x | (v.z << 16); }
                    #pragma unroll
                    for (int w = 0; w < 8; w++) { uint4 v = __ldcs(c2 + w); pk2[w] = v.x | (v.z << 16); }
                } else {
                    const uint4* c1 = (const uint4*)x1 + (pb >> 1);
                    const uint4* c2 = (const uint4*)x2 + (pb >> 1);
                    #pragma unroll
                    for (int w = 0; w < 4; w++) {
                        uint4 v = __ldcs(c1 + w);
                        pk1[2*w] = v.x | (v.y << 16); pk1[2*w+1] = v.z | (v.w << 16);
                    }
                    #pragma unroll
                    for (int w = 0; w < 4; w++) {
                        uint4 v = __ldcs(c2 + w);
                        pk2[2*w] = v.x | (v.y << 16); pk2[2*w+1] = v.z | (v.w << 16);
                    }
                }
                ((uint4*)(g_cx1 + pb))[0] = make_uint4(pk1[0], pk1[1], pk1[2], pk1[3]);
                ((uint4*)(g_cx1 + pb))[1] = make_uint4(pk1[4], pk1[5], pk1[6], pk1[7]);
                ((uint4*)(g_cx2 + pb))[0] = make_uint4(pk2[0], pk2[1], pk2[2], pk2[3]);
                ((uint4*)(g_cx2 + pb))[1] = make_uint4(pk2[4], pk2[5], pk2[6], pk2[7]);
            } else {
                const uint4* c1 = (const uint4*)(g_cx1 + pb);
                const uint4* c2 = (const uint4*)(g_cx2 + pb);
                uint4 q0 = __ldg(c1), q1 = __ldg(c1 + 1);
                uint4 r0 = __ldg(c2), r1 = __ldg(c2 + 1);
                pk1[0]=q0.x; pk1[1]=q0.y; pk1[2]=q0.z; pk1[3]=q0.w;
                pk1[4]=q1.x; pk1[5]=q1.y; pk1[6]=q1.z; pk1[7]=q1.w;
                pk2[0]=r0.x; pk2[1]=r0.y; pk2[2]=r0.z; pk2[3]=r0.w;
                pk2[4]=r1.x; pk2[5]=r1.y; pk2[6]=r1.z; pk2[7]=r1.w;
            }
            __half2 f1a, f1b, f2a, f2b;
            gath8(pk1, tabh, f1a, f1b);
            gath8(pk2, tabh, f2a, f2b);
            F1h[j*33 + lane] = make_uint2(*(unsigned*)&f1a, *(unsigned*)&f1b);
            float2 lo = __half22float2(f2a), hi = __half22float2(f2b);
            F2f[lane*67 + j] = make_float4(lo.x, lo.y, hi.x, hi.y);
        }
        __syncthreads();

        // ======== phase 2: derived = pi1.F1 + pi2.F2 - F1.(pi@F2), f32x2 ========
        {
            ull mv00 = 0ull, mv01 = 0ull, mv10 = 0ull, mv11 = 0ull;  // [n][b01/b23]
            const ulonglong2* fbA = (const ulonglong2*)(F2f + g8*67);
            const ulonglong2* fbB = (const ulonglong2*)(F2f + (g8+16)*67);
            #pragma unroll 4
            for (int kp = 0; kp < 32; kp++) {
                float2 pw = __half22float2(piPh[kp*64 + jj]);
                ull pwx = pack2(pw.x, pw.x);
                ull pwy = pack2(pw.y, pw.y);
                ulonglong2 A0 = fbA[2*kp], B0 = fbA[2*kp + 1];   // k=2kp, 2kp+1 (n=g8)
                ulonglong2 A1 = fbB[2*kp], B1 = fbB[2*kp + 1];   // (n=g8+16)
                fma2(mv00, pwx, A0.x); fma2(mv01, pwx, A0.y);
                fma2(mv00, pwy, B0.x); fma2(mv01, pwy, B0.y);
                fma2(mv10, pwx, A1.x); fma2(mv11, pwx, A1.y);
                fma2(mv10, pwy, B1.x); fma2(mv11, pwy, B1.y);
            }
            const float p1 = pi1s[jj], p2 = pi2s[jj];
            #pragma unroll
            for (int r = 0; r < 2; r++) {
                const int n = g8 + r*16;
                float2 ma = unpack2(r ? mv10 : mv00);
                float2 mb = unpack2(r ? mv11 : mv01);
                uint2 hp = F1h[jj*33 + n];
                float2 f01 = __half22float2(*(__half2*)&hp.x);
                float2 f23 = __half22float2(*(__half2*)&hp.y);
                float4 f2v = F2f[n*67 + jj];
                float4 c;
                c.x = p1*f01.x + p2*f2v.x - f01.x*ma.x;
                c.y = p1*f01.y + p2*f2v.y - f01.y*ma.y;
                c.z = p1*f23.x + p2*f2v.z - f23.x*mb.x;
                c.w = p1*f23.y + p2*f2v.w - f23.y*mb.y;
                #pragma unroll
                for (int off = 16; off > 0; off >>= 1) {
                    c.x += __shfl_xor_sync(0xFFFFFFFFu, c.x, off);
                    c.y += __shfl_xor_sync(0xFFFFFFFFu, c.y, off);
                    c.z += __shfl_xor_sync(0xFFFFFFFFu, c.z, off);
                    c.w += __shfl_xor_sync(0xFFFFFFFFu, c.w, off);
                }
                if (lane == 0) red4[n*2 + half] = c;
            }
        }
        pend_n0 = n0;
        // loop-top barrier orders red4 writes vs next finalize
    }
}

// ---------------- launcher ----------------------------------------------------
extern "C" void kernel_launch(void* const* d_in, const int* in_sizes, int n_in,
                              void* d_out, int out_size) {
    const float* a0 = (const float*)d_in[0];
    const float* Wm = (const float*)d_in[1];
    const void*  x1 = d_in[2];
    const void*  x2 = d_in[3];
    float* out = (float*)d_out;

    cudaFuncSetAttribute(k_iter<0>, cudaFuncAttributeMaxDynamicSharedMemorySize, SMEM_TOTAL);
    cudaFuncSetAttribute(k_iter<1>, cudaFuncAttributeMaxDynamicSharedMemorySize, SMEM_TOTAL);

    k_iter<0><<<NBLK, NT, SMEM_TOTAL>>>(a0, Wm, x1, x2, out);  // raw X -> packed + tabB
    k_iter<1><<<NBLK, NT, SMEM_TOTAL>>>(a0, Wm, x1, x2, out);  // packed -> out
}

// round 10
// speedup vs baseline: 1.0762x; 1.0762x over previous
#include <cuda_runtime.h>
#include <cuda_fp16.h>
#include <cstdint>

#define NN 20000
#define MM 64
#define WL 8
#define NPAIRS (MM*NN*WL)      /* 10,240,000 pairs per X tensor */
#define NPB 16                 /* n's per chunk (small for stage ring) */
#define NCHUNK (NN/NPB)        /* 1250 */
#define NBLK 148               /* one block per SM */
#define NT 1024                /* 16 producer warps + 16 consumer warps */
#define NPROD 512
#define NSTG 2

/* ---- stage: F1h [64][17] uint2 (8704 B) + F2f [16][67] float4 (17152 B) ---- */
#define STG_F2_OFF 8704
#define STG_BYTES  25856

/* ---- shared memory layout (bytes) ---- */
#define OFF_STG   (NN*8)                     /* 160000 : table first            */
#define OFF_PIP   (OFF_STG + NSTG*STG_BYTES) /* 211712 : piP half2[32*64]       */
#define OFF_P12   (OFF_PIP + 8192)           /* 219904 : pi1, pi2               */
#define OFF_RED   (OFF_P12 + 512)            /* 220416 : float4[16][2]          */
#define OFF_CTL   (OFF_RED + 512)            /* 220928 : hdr[2] + 4 mbarriers   */
#define SMEM_TOTAL (OFF_CTL + 128)           /* 221056 */

typedef unsigned long long ull;

// ---------------- device scratch (static) ------------------------------------
__device__ unsigned g_cx1[NPAIRS];   // packed (i0 | i1<<16)
__device__ unsigned g_cx2[NPAIRS];
__device__ uint2    g_tabB[NN];      // intermediate a after iter 0 (half x 4 batches)
__device__ int      g_tick[2] = {0, 0};

// ---------------- small helpers ----------------------------------------------
__device__ __forceinline__ unsigned s2u(const void* p) {
    return (unsigned)__cvta_generic_to_shared(p);
}
__device__ __forceinline__ void mbar_init(unsigned a, unsigned cnt) {
    asm volatile("mbarrier.init.shared.b64 [%0], %1;" :: "r"(a), "r"(cnt) : "memory");
}
__device__ __forceinline__ void mbar_arrive(unsigned a) {
    asm volatile("mbarrier.arrive.shared.b64 _, [%0];" :: "r"(a) : "memory");
}
__device__ __forceinline__ void mbar_wait(unsigned a, unsigned parity) {
    asm volatile(
        "{\n\t.reg .pred P;\n\t"
        "WL_%=:\n\t"
        "mbarrier.try_wait.parity.acquire.cta.shared::cta.b64 P, [%0], %1, 0x989680;\n\t"
        "@P bra.uni WD_%=;\n\t"
        "bra.uni WL_%=;\n\t"
        "WD_%=:\n\t}"
        :: "r"(a), "r"(parity) : "memory");
}
__device__ __forceinline__ ull pack2(float lo, float hi) {
    ull r; asm("mov.b64 %0, {%1, %2};" : "=l"(r) : "f"(lo), "f"(hi)); return r;
}
__device__ __forceinline__ float2 unpack2(ull v) {
    float2 f; asm("mov.b64 {%0, %1}, %2;" : "=f"(f.x), "=f"(f.y) : "l"(v)); return f;
}
__device__ __forceinline__ void fma2(ull& d, ull a, ull b) {
    asm("fma.rn.f32x2 %0, %1, %2, %0;" : "+l"(d) : "l"(a), "l"(b));
}
// gather: 8 independent products, max tree
__device__ __forceinline__ void gath8(const unsigned* pk, const uint2* __restrict__ tab,
                                      __half2& ga, __half2& gb) {
    __half2 px[8], py[8];
    #pragma unroll
    for (int w = 0; w < 8; w++) {
        uint2 A = tab[pk[w] & 0xFFFFu];
        uint2 B = tab[pk[w] >> 16];
        px[w] = __hmul2(*(__half2*)&A.x, *(__half2*)&B.x);
        py[w] = __hmul2(*(__half2*)&A.y, *(__half2*)&B.y);
    }
    #pragma unroll
    for (int s = 4; s > 0; s >>= 1)
        #pragma unroll
        for (int w = 0; w < s; w++) {
            px[w] = __hmax2(px[w], px[w + s]);
            py[w] = __hmax2(py[w], py[w + s]);
        }
    ga = px[0]; gb = py[0];
}

// ---------------- main iteration kernel --------------------------------------
template<int ITER>
__global__ void __launch_bounds__(NT, 1) k_iter(const float* __restrict__ a0,
                                                const float* __restrict__ Wm,
                                                const void* __restrict__ x1,
                                                const void* __restrict__ x2,
                                                float* __restrict__ out) {
    extern __shared__ char smem[];
    uint2*    tabh = (uint2*)smem;                    // [NN]
    __half2*  piPh = (__half2*)(smem + OFF_PIP);      // [32*64]
    float*    pi1s = (float*) (smem + OFF_P12);
    float*    pi2s = pi1s + MM;
    float4*   red4 = (float4*)(smem + OFF_RED);       // [16][2]
    float*    redf = (float*) (smem + OFF_RED);
    volatile int* hdr = (volatile int*)(smem + OFF_CTL);  // [2]
    const unsigned mb_full0  = s2u(smem + OFF_CTL + 16);
    const unsigned mb_full1  = s2u(smem + OFF_CTL + 24);
    const unsigned mb_empty0 = s2u(smem + OFF_CTL + 32);
    const unsigned mb_empty1 = s2u(smem + OFF_CTL + 40);

    const int tid  = threadIdx.x;
    const int warp = tid >> 5, lane = tid & 31;

    // reset the OTHER iter's ticket for the next launch/replay
    if (blockIdx.x == 0 && tid == 0) g_tick[ITER ^ 1] = 0;
    if (tid == 0) {
        mbar_init(mb_full0,  NPROD); mbar_init(mb_full1,  NPROD);
        mbar_init(mb_empty0, NPROD); mbar_init(mb_empty1, NPROD);
    }

    // ===== preamble (all 1024 threads): a-table =====
    if (ITER == 0) {
        for (int i = tid; i < NN; i += NT) {
            __half2 h01 = __floats2half2_rn(__ldg(a0 + i),        __ldg(a0 + NN + i));
            __half2 h23 = __floats2half2_rn(__ldg(a0 + 2*NN + i), __ldg(a0 + 3*NN + i));
            tabh[i] = make_uint2(*(unsigned*)&h01, *(unsigned*)&h23);
        }
    } else {
        for (int i = tid; i < NN; i += NT) tabh[i] = g_tabB[i];
    }

    // ===== preamble: softmax over 64x64 W (scratch = stage area, pre-roles) =====
    {
        float* sp = (float*)(smem + OFF_STG);
        float v4[4];
        float lm = -1e30f;
        #pragma unroll
        for (int t = 0; t < 4; t++) {
            float v = __ldg(Wm + tid + t*NT);
            v4[t] = v;
            lm = fmaxf(lm, v);
        }
        #pragma unroll
        for (int off = 16; off > 0; off >>= 1)
            lm = fmaxf(lm, __shfl_xor_sync(0xFFFFFFFFu, lm, off));
        if (lane == 0) redf[warp] = lm;
        __syncthreads();
        float m = -1e30f;
        #pragma unroll
        for (int w = 0; w < 32; w++) m = fmaxf(m, redf[w]);
        __syncthreads();
        float ls = 0.f;
        #pragma unroll
        for (int t = 0; t < 4; t++) {
            float e = expf(v4[t] - m);
            sp[tid + t*NT] = e;
            ls += e;
        }
        #pragma unroll
        for (int off = 16; off > 0; off >>= 1)
            ls += __shfl_xor_sync(0xFFFFFFFFu, ls, off);
        if (lane == 0) redf[32 + warp] = ls;
        __syncthreads();
        float tot = 0.f;
        #pragma unroll
        for (int w = 0; w < 32; w++) tot += redf[32 + w];
        const float inv = 1.f / tot;

        for (int i = tid; i < 2048; i += NT) {
            int kp = i >> 6, j = i & 63;
            piPh[i] = __floats2half2_rn(sp[j*MM + 2*kp] * inv, sp[j*MM + 2*kp + 1] * inv);
        }
        if (tid < MM) {
            float s = 0.f;
            #pragma unroll 16
            for (int k = 0; k < MM; k++) s += sp[tid*MM + k];
            pi1s[tid] = s * inv;
        } else if (tid < 2*MM) {
            int k = tid - MM;
            float s = 0.f;
            #pragma unroll 16
            for (int j = 0; j < MM; j++) s += sp[j*MM + k];
            pi2s[k] = s * inv;
        }
    }

    // ===== preamble: dtype probe (iter 0 only) =====
    int is64 = 0;
    if (ITER == 0) {
        const unsigned* x1u = (const unsigned*)x1;
        int nz = (x1u[2*tid + 1] != 0u) | (x1u[2*(tid + NT) + 1] != 0u);
        is64 = !__syncthreads_or(nz);
    }
    __syncthreads();   // softmax scratch dead; tab/piP/pi/mbar visible to all

    int* tick = &g_tick[ITER];

    if (tid < NPROD) {
        // ===================== PRODUCER: gathers -> stage ring =====================
        const int pwarp = warp;            // 0..15
        const int h  = lane >> 4;          // 0/1: which j of the pair
        const int nl = lane & 15;          // n within chunk
        for (int i = 0; ; i++) {
            const int s = i & 1, ks = i >> 1;
            if (ks >= 1) mbar_wait(s ? mb_empty1 : mb_empty0, (ks - 1) & 1);
            if (tid == 0) hdr[s] = atomicAdd(tick, 1);
            asm volatile("bar.sync 1, %0;" :: "n"(NPROD) : "memory");
            const int chunk = hdr[s];
            if (chunk >= NCHUNK) { mbar_arrive(s ? mb_full1 : mb_full0); break; }
            const int n0 = chunk * NPB;
            uint2*  F1h = (uint2*) (smem + OFF_STG + s*STG_BYTES);
            float4* F2f = (float4*)(smem + OFF_STG + s*STG_BYTES + STG_F2_OFF);

            #pragma unroll
            for (int p = 0; p < 2; p++) {
                const int j = p*32 + pwarp*2 + h;
                const size_t pb = ((size_t)j * NN + n0 + nl) * WL;
                unsigned pk1[8], pk2[8];
                if (ITER == 0) {
                    if (is64) {
                        const uint4* c1 = (const uint4*)x1 + pb;
                        const uint4* c2 = (const uint4*)x2 + pb;
                        #pragma unroll
                        for (int w = 0; w < 8; w++) { uint4 v = __ldcs(c1 + w); pk1[w] = v.x | (v.z << 16); }
                        #pragma unroll
                        for (int w = 0; w < 8; w++) { uint4 v = __ldcs(c2 + w); pk2[w] = v.x | (v.z << 16); }
                    } else {
                        const uint4* c1 = (const uint4*)x1 + (pb >> 1);
                        const uint4* c2 = (const uint4*)x2 + (pb >> 1);
                        #pragma unroll
                        for (int w = 0; w < 4; w++) {
                            uint4 v = __ldcs(c1 + w);
                            pk1[2*w] = v.x | (v.y << 16); pk1[2*w+1] = v.z | (v.w << 16);
                        }
                        #pragma unroll
                        for (int w = 0; w < 4; w++) {
                            uint4 v = __ldcs(c2 + w);
                            pk2[2*w] = v.x | (v.y << 16); pk2[2*w+1] = v.z | (v.w << 16);
                        }
                    }
                    ((uint4*)(g_cx1 + pb))[0] = make_uint4(pk1[0], pk1[1], pk1[2], pk1[3]);
                    ((uint4*)(g_cx1 + pb))[1] = make_uint4(pk1[4], pk1[5], pk1[6], pk1[7]);
                    ((uint4*)(g_cx2 + pb))[0] = make_uint4(pk2[0], pk2[1], pk2[2], pk2[3]);
                    ((uint4*)(g_cx2 + pb))[1] = make_uint4(pk2[4], pk2[5], pk2[6], pk2[7]);
                } else {
                    const uint4* c1 = (const uint4*)(g_cx1 + pb);
                    const uint4* c2 = (const uint4*)(g_cx2 + pb);
                    uint4 q0 = __ldg(c1), q1 = __ldg(c1 + 1);
                    uint4 r0 = __ldg(c2), r1 = __ldg(c2 + 1);
                    pk1[0]=q0.x; pk1[1]=q0.y; pk1[2]=q0.z; pk1[3]=q0.w;
                    pk1[4]=q1.x; pk1[5]=q1.y; pk1[6]=q1.z; pk1[7]=q1.w;
                    pk2[0]=r0.x; pk2[1]=r0.y; pk2[2]=r0.z; pk2[3]=r0.w;
                    pk2[4]=r1.x; pk2[5]=r1.y; pk2[6]=r1.z; pk2[7]=r1.w;
                }
                __half2 f1a, f1b, f2a, f2b;
                gath8(pk1, tabh, f1a, f1b);
                gath8(pk2, tabh, f2a, f2b);
                F1h[j*17 + nl] = make_uint2(*(unsigned*)&f1a, *(unsigned*)&f1b);
                float2 lo = __half22float2(f2a), hi = __half22float2(f2b);
                F2f[nl*67 + j] = make_float4(lo.x, lo.y, hi.x, hi.y);
            }
            mbar_arrive(s ? mb_full1 : mb_full0);
        }
    } else {
        // ===================== CONSUMER: bilinear + reduce + finalize ==============
        const int ctid = tid - NPROD;          // 0..511
        const int cwarp = ctid >> 5;           // 0..15
        const int jj = ctid & 63;              // pi column
        const int g8 = ctid >> 6;              // 0..7 -> n = g8, g8+8
        const int half = cwarp & 1;
        for (int i = 0; ; i++) {
            const int s = i & 1, ks = i >> 1;
            mbar_wait(s ? mb_full1 : mb_full0, ks & 1);
            const int chunk = hdr[s];
            if (chunk >= NCHUNK) break;
            const int n0 = chunk * NPB;
            uint2*  F1h = (uint2*) (smem + OFF_STG + s*STG_BYTES);
            float4* F2f = (float4*)(smem + OFF_STG + s*STG_BYTES + STG_F2_OFF);

            ull mv00 = 0ull, mv01 = 0ull, mv10 = 0ull, mv11 = 0ull;   // [n][b01/b23]
            const ulonglong2* fbA = (const ulonglong2*)(F2f + g8*67);
            const ulonglong2* fbB = (const ulonglong2*)(F2f + (g8+8)*67);
            #pragma unroll 4
            for (int kp = 0; kp < 32; kp++) {
                float2 pw = __half22float2(piPh[kp*64 + jj]);
                ull pwx = pack2(pw.x, pw.x);
                ull pwy = pack2(pw.y, pw.y);
                ulonglong2 A0 = fbA[2*kp], B0 = fbA[2*kp + 1];
                ulonglong2 A1 = fbB[2*kp], B1 = fbB[2*kp + 1];
                fma2(mv00, pwx, A0.x); fma2(mv01, pwx, A0.y);
                fma2(mv00, pwy, B0.x); fma2(mv01, pwy, B0.y);
                fma2(mv10, pwx, A1.x); fma2(mv11, pwx, A1.y);
                fma2(mv10, pwy, B1.x); fma2(mv11, pwy, B1.y);
            }
            const float p1 = pi1s[jj], p2 = pi2s[jj];
            #pragma unroll
            for (int r = 0; r < 2; r++) {
                const int n = g8 + r*8;
                float2 ma = unpack2(r ? mv10 : mv00);
                float2 mb = unpack2(r ? mv11 : mv01);
                uint2 hp = F1h[jj*17 + n];
                float2 f01 = __half22float2(*(__half2*)&hp.x);
                float2 f23 = __half22float2(*(__half2*)&hp.y);
                float4 f2v = F2f[n*67 + jj];
                float4 c;
                c.x = p1*f01.x + p2*f2v.x - f01.x*ma.x;
                c.y = p1*f01.y + p2*f2v.y - f01.y*ma.y;
                c.z = p1*f23.x + p2*f2v.z - f23.x*mb.x;
                c.w = p1*f23.y + p2*f2v.w - f23.y*mb.y;
                #pragma unroll
                for (int off = 16; off > 0; off >>= 1) {
                    c.x += __shfl_xor_sync(0xFFFFFFFFu, c.x, off);
                    c.y += __shfl_xor_sync(0xFFFFFFFFu, c.y, off);
                    c.z += __shfl_xor_sync(0xFFFFFFFFu, c.z, off);
                    c.w += __shfl_xor_sync(0xFFFFFFFFu, c.w, off);
                }
                if (lane == 0) red4[n*2 + half] = c;
            }
            asm volatile("bar.sync 2, %0;" :: "n"(NPROD) : "memory");
            // stage reads done -> release it to producers
            mbar_arrive(s ? mb_empty1 : mb_empty0);

            // finalize: a' = 1 - (1-a)(1-derived)
            if (ITER == 0) {
                if (ctid < NPB) {
                    const int n = n0 + ctid;
                    float4 d0 = red4[ctid*2], d1 = red4[ctid*2 + 1];
                    uint2 u = tabh[n];
                    float2 a01 = __half22float2(*(__half2*)&u.x);
                    float2 a23 = __half22float2(*(__half2*)&u.y);
                    __half2 h01 = __floats2half2_rn(
                        1.f - (1.f - a01.x) * (1.f - (d0.x + d1.x)),
                        1.f - (1.f - a01.y) * (1.f - (d0.y + d1.y)));
                    __half2 h23 = __floats2half2_rn(
                        1.f - (1.f - a23.x) * (1.f - (d0.z + d1.z)),
                        1.f - (1.f - a23.y) * (1.f - (d0.w + d1.w)));
                    g_tabB[n] = make_uint2(*(unsigned*)&h01, *(unsigned*)&h23);
                }
            } else {
                if (ctid < 4*NPB) {
                    const int b = ctid >> 4, nl = ctid & 15;
                    const int n = n0 + nl;
                    float dv = redf[nl*8 + b] + redf[nl*8 + 4 + b];
                    float av = __half2float(((const __half*)smem)[n*4 + b]);
                    out[b*NN + n] = 1.f - (1.f - av) * (1.f - dv);
                }
            }
            asm volatile("bar.sync 2, %0;" :: "n"(NPROD) : "memory");  // red safe for next chunk
        }
    }
}

// ---------------- launcher ----------------------------------------------------
extern "C" void kernel_launch(void* const* d_in, const int* in_sizes, int n_in,
                              void* d_out, int out_size) {
    const float* a0 = (const float*)d_in[0];
    const float* Wm = (const float*)d_in[1];
    const void*  x1 = d_in[2];
    const void*  x2 = d_in[3];
    float* out = (float*)d_out;

    cudaFuncSetAttribute(k_iter<0>, cudaFuncAttributeMaxDynamicSharedMemorySize, SMEM_TOTAL);
    cudaFuncSetAttribute(k_iter<1>, cudaFuncAttributeMaxDynamicSharedMemorySize, SMEM_TOTAL);

    k_iter<0><<<NBLK, NT, SMEM_TOTAL>>>(a0, Wm, x1, x2, out);  // raw X -> packed + tabB
    k_iter<1><<<NBLK, NT, SMEM_TOTAL>>>(a0, Wm, x1, x2, out);  // packed -> out
}